// round 17
// baseline (speedup 1.0000x reference)
#include <cuda_runtime.h>
#include <cstdint>

#define NT  64
#define NPB 64
#define SMS 65   // (s*65 + p) % 32 = (s + p) % 32
#define NITER 5
#define DUMMY (91 * SMS)   // sink slot base for non-canonical (duplicate) fill stores

// packed symmetric index for 13x13 (upper triangle), compile-time after unroll
__device__ __forceinline__ int sidx(int r, int c) {
    int lo = r < c ? r : c;
    int hi = r < c ? c : r;
    return lo * 13 - (lo * (lo - 1)) / 2 + (hi - lo);
}

#define MM(r, c) sm[sidx((r), (c)) * SMS + tid]

// accumulate P[r,I]*w[j] into upper-tri Q (I is a literal)
#define ACC(I, P) do { const float p_ = (P); _Pragma("unroll") \
    for (int j = (I); j < 7; j++) Q[(I)][j] += p_ * w[j]; } while (0)

// specialized T0 row: Q[I][j] += SGN * w_row(R)[j]; unused w entries are DCE'd
#define SPECROW(R, I, SGNF) do { \
    float w_[7]; \
    w_[0] = MM(R,7)  - MM(R,5); \
    w_[1] = MM(R,2)  - MM(R,6); \
    w_[2] = MM(R,3)  - MM(R,1); \
    w_[3] = MM(R,10); \
    w_[4] = MM(R,11); \
    w_[5] = MM(R,12); \
    w_[6] = MM(R,0) + MM(R,4) + MM(R,8) + MM(R,9) + MM(R,12); \
    _Pragma("unroll") \
    for (int j = (I); j < 7; j++) Q[(I)][j] += (SGNF) * w_[j]; \
} while (0)

__global__ void __launch_bounds__(NT, 9)
mtm_refine_kernel(const float* __restrict__ Min, const float* __restrict__ Tin,
                  float* __restrict__ outT, float* __restrict__ outOm, int N)
{
    __shared__ float sm[91 * SMS + NPB];      // 23,916 B (incl. dummy sink row)
    __shared__ unsigned short lut[169];       // canonical: s*SMS ; duplicate: DUMMY

    const int tid  = threadIdx.x;
    const int base = blockIdx.x * NPB;

    // ---- element->slot LUT: canonical -> packed slot, duplicate -> dummy sink ----
    for (int e = tid; e < 169; e += NT) {
        const int r = e / 13, c = e - (e / 13) * 13;
        lut[e] = (r <= c)
            ? (unsigned short)((r * 13 - ((r * (r - 1)) >> 1) + (c - r)) * SMS)
            : (unsigned short)DUMMY;
    }
    __syncthreads();

    // ---- vectorized cooperative fill (float4 LDG + LUT STS; duplicates merge at DUMMY+p) ----
    {
        int np = N - base; if (np > NPB) np = NPB;
        const int limit  = np * 169;
        const int limit4 = limit >> 2;
        const float4* g4 = (const float4*)(Min + (size_t)base * 169);

        int p = 0, e = 4 * tid;
        if (e >= 169) { e -= 169; p++; }     // 4*tid <= 252 < 338
        for (int i4 = tid; i4 < limit4; i4 += NT) {
            const float4 v = g4[i4];
            int ek = e, pk = p;
            if (ek >= 169) { ek -= 169; pk++; } sm[(int)lut[ek] + pk] = v.x; ek++;
            if (ek >= 169) { ek -= 169; pk++; } sm[(int)lut[ek] + pk] = v.y; ek++;
            if (ek >= 169) { ek -= 169; pk++; } sm[(int)lut[ek] + pk] = v.z; ek++;
            if (ek >= 169) { ek -= 169; pk++; } sm[(int)lut[ek] + pk] = v.w;
            // advance by 4*NT = 256 = 169 + 87
            e += 87; p += 1;
            if (e >= 169) { e -= 169; p += 1; }
        }
        for (int idx = limit4 * 4 + tid; idx < limit; idx += NT) {
            const int pp = idx / 169;
            sm[(int)lut[idx - pp * 169] + pp] = Min[(size_t)base * 169 + idx];
        }
    }
    __syncthreads();

    const int gp = base + tid;
    if (gp >= N) return;

    // ---- load T rows 0..2: (ta,tb,tc,td)[k] ----
    float ta[3], tb[3], tc[3], td[3];
    {
        const float4* gT = (const float4*)(Tin + (size_t)gp * 16);
        #pragma unroll
        for (int k = 0; k < 3; k++) {
            float4 f = gT[k];
            ta[k] = f.x; tb[k] = f.y; tc[k] = f.z; td[k] = f.w;
        }
    }

    // T0 = identity pose with t_z = 1 (exact fp32). All dataset problems start here;
    // the guard keeps the kernel correct for arbitrary T.
    const bool isT0 =
        ta[0] == 1.0f && tb[0] == 0.0f && tc[0] == 0.0f && td[0] == 0.0f &&
        ta[1] == 0.0f && tb[1] == 1.0f && tc[1] == 0.0f && td[1] == 0.0f &&
        ta[2] == 0.0f && tb[2] == 0.0f && tc[2] == 1.0f && td[2] == 1.0f;

    float OmU[6][6];   // upper-tri Omega of last iteration

    #pragma unroll 1   // 5 GN iterations (reference count); bound I$ footprint
    for (int it = 0; it < NITER; ++it) {
        float Q[7][7];
        #pragma unroll
        for (int i = 0; i < 7; i++)
            #pragma unroll
            for (int j = i; j < 7; j++) Q[i][j] = 0.0f;

        if (it == 0 && isT0) {
            // ---- specialized first sweep at T0: P entries are 0/±1, rows 0,4,8,9 drop ----
            SPECROW(1, 2, -1.0f);
            SPECROW(2, 1,  1.0f);
            SPECROW(3, 2,  1.0f);
            SPECROW(5, 0, -1.0f);
            SPECROW(6, 1, -1.0f);
            SPECROW(7, 0,  1.0f);
            SPECROW(10, 3, 1.0f);
            SPECROW(11, 4, 1.0f);
            SPECROW(12, 5, 1.0f);
        } else {
            // ---- generic single sweep over M rows (row 9 only feeds unused Q[6][6]) ----
            #pragma unroll
            for (int r = 0; r < 13; r++) {
                if (r == 9) continue;
                float m[13];
                #pragma unroll
                for (int c = 0; c < 13; c++) m[c] = MM(r, c);

                float w[7];
                w[0] = 0.f; w[1] = 0.f; w[2] = 0.f; w[6] = 0.f;
                #pragma unroll
                for (int k = 0; k < 3; k++) {
                    w[0] += tc[k]*m[3*k+1] - tb[k]*m[3*k+2];
                    w[1] += ta[k]*m[3*k+2] - tc[k]*m[3*k+0];
                    w[2] += tb[k]*m[3*k+0] - ta[k]*m[3*k+1];
                    w[6] += ta[k]*m[3*k+0] + tb[k]*m[3*k+1] + tc[k]*m[3*k+2];
                }
                w[3] = ta[0]*m[10] + ta[1]*m[11] + ta[2]*m[12];
                w[4] = tb[0]*m[10] + tb[1]*m[11] + tb[2]*m[12];
                w[5] = tc[0]*m[10] + tc[1]*m[11] + tc[2]*m[12];
                w[6] += m[9] + td[0]*m[10] + td[1]*m[11] + td[2]*m[12];

                if (r < 9) {
                    const int k = r / 3, rr = r - 3 * k;
                    if (rr == 0)      { ACC(1, -tc[k]); ACC(2,  tb[k]); }
                    else if (rr == 1) { ACC(0,  tc[k]); ACC(2, -ta[k]); }
                    else              { ACC(0, -tb[k]); ACC(1,  ta[k]); }
                } else {
                    const int k = r - 10;
                    ACC(3, ta[k]); ACC(4, tb[k]); ACC(5, tc[k]);
                }
            }
        }

        // ---- regularization (matches reference) ----
        const float regT = 1e-8f * fmaxf(Q[3][3] + Q[4][4] + Q[5][5], 1.0f);
        #pragma unroll
        for (int i = 0; i < 6; i++) {
            const float dd = (i < 3) ? 10.0f : regT;
            #pragma unroll
            for (int j = i; j < 6; j++)
                OmU[i][j] = Q[i][j] + ((i == j) ? dd : 0.0f);
        }
        float mx = OmU[0][0];
        #pragma unroll
        for (int i = 0; i < 6; i++)
            #pragma unroll
            for (int j = i; j < 6; j++) mx = fmaxf(mx, OmU[i][j]);
        const float reg = 1e-5f * (1.0f + mx);

        float A[6][6];   // upper-tri only
        #pragma unroll
        for (int i = 0; i < 6; i++)
            #pragma unroll
            for (int j = i; j < 6; j++)
                A[i][j] = OmU[i][j] + ((i == j) ? reg : 0.0f);

        // ---- Cholesky solve A v' = q ; v = -v' ----
        float L[6][6], di[6];
        #pragma unroll
        for (int j = 0; j < 6; j++) {
            float s = A[j][j];
            #pragma unroll
            for (int k = 0; k < j; k++) s -= L[j][k] * L[j][k];
            di[j] = rsqrtf(s);
            #pragma unroll
            for (int i = j + 1; i < 6; i++) {
                float t = A[j][i];
                #pragma unroll
                for (int k = 0; k < j; k++) t -= L[i][k] * L[j][k];
                L[i][j] = t * di[j];
            }
        }
        float z[6];
        #pragma unroll
        for (int i = 0; i < 6; i++) {
            float s = Q[i][6];              // q[i]
            #pragma unroll
            for (int k = 0; k < i; k++) s -= L[i][k] * z[k];
            z[i] = s * di[i];
        }
        float w6v[6];
        #pragma unroll
        for (int ii = 5; ii >= 0; ii--) {
            float s = z[ii];
            #pragma unroll
            for (int k = ii + 1; k < 6; k++) s -= L[k][ii] * w6v[k];
            w6v[ii] = s * di[ii];
        }

        const float vx = -w6v[0], vy = -w6v[1], vz = -w6v[2];
        const float px = -w6v[3], py = -w6v[4], pz = -w6v[5];

        // ---- closed-form SE(3) exponential ----
        const float th2 = vx*vx + vy*vy + vz*vz;
        float sA, sB, sC;
        if (th2 > 1e-2f) {
            const float th = sqrtf(th2);
            float sn, cn;
            __sincosf(th, &sn, &cn);
            sA = sn / th;
            sB = (1.0f - cn) / th2;
            sC = (1.0f - sA) / th2;
        } else {
            sA = 1.0f - th2 * (1.0f/6.0f)  + th2*th2 * (1.0f/120.0f);
            sB = 0.5f - th2 * (1.0f/24.0f) + th2*th2 * (1.0f/720.0f);
            sC = (1.0f/6.0f) - th2 * (1.0f/120.0f) + th2*th2 * (1.0f/5040.0f);
        }
        const float k00 = -(vy*vy + vz*vz), k11 = -(vx*vx + vz*vz), k22 = -(vx*vx + vy*vy);
        const float kxy = vx*vy, kxz = vx*vz, kyz = vy*vz;

        const float R00 = 1.0f + sB*k00, R01 = -sA*vz + sB*kxy, R02 =  sA*vy + sB*kxz;
        const float R10 =  sA*vz + sB*kxy, R11 = 1.0f + sB*k11, R12 = -sA*vx + sB*kyz;
        const float R20 = -sA*vy + sB*kxz, R21 =  sA*vx + sB*kyz, R22 = 1.0f + sB*k22;

        const float V00 = 1.0f + sC*k00, V01 = -sB*vz + sC*kxy, V02 =  sB*vy + sC*kxz;
        const float V10 =  sB*vz + sC*kxy, V11 = 1.0f + sC*k11, V12 = -sB*vx + sC*kyz;
        const float V20 = -sB*vy + sC*kxz, V21 =  sB*vx + sC*kyz, V22 = 1.0f + sC*k22;

        const float et0 = V00*px + V01*py + V02*pz;
        const float et1 = V10*px + V11*py + V12*pz;
        const float et2 = V20*px + V21*py + V22*pz;

        // ---- T <- T @ expm(hat(v)) (rows 0..2; row 3 unchanged) ----
        #pragma unroll
        for (int k = 0; k < 3; k++) {
            const float r0 = ta[k], r1 = tb[k], r2 = tc[k], r3 = td[k];
            ta[k] = r0*R00 + r1*R10 + r2*R20;
            tb[k] = r0*R01 + r1*R11 + r2*R21;
            tc[k] = r0*R02 + r1*R12 + r2*R22;
            td[k] = r0*et0 + r1*et1 + r2*et2 + r3;
        }
    }

    // ---- outputs (float32): T, then Omega / (t_z^2 + 1e-8) ----
    const float tzf = td[2];
    const float sc  = 1.0f / (tzf * tzf + 1e-8f);

    float4* oT = (float4*)(outT + (size_t)gp * 16);
    #pragma unroll
    for (int k = 0; k < 3; k++)
        oT[k] = make_float4(ta[k], tb[k], tc[k], td[k]);
    // last row of T unchanged by boxplus (expm row3 = [0,0,0,1])
    oT[3] = ((const float4*)(Tin + (size_t)gp * 16))[3];

    float Of[36];
    #pragma unroll
    for (int i = 0; i < 6; i++)
        #pragma unroll
        for (int j = 0; j < 6; j++)
            Of[i*6 + j] = ((i <= j) ? OmU[i][j] : OmU[j][i]) * sc;

    float4* oO = (float4*)(outOm + (size_t)gp * 36);
    #pragma unroll
    for (int v4 = 0; v4 < 9; v4++)
        oO[v4] = make_float4(Of[v4*4+0], Of[v4*4+1], Of[v4*4+2], Of[v4*4+3]);
}

extern "C" void kernel_launch(void* const* d_in, const int* in_sizes, int n_in,
                              void* d_out, int out_size)
{
    const float* Min = (const float*)d_in[0];   // MTMs [B,C,13,13] fp32
    const float* Tin = (const float*)d_in[1];   // Ts   [B,C,4,4]   fp32
    const int N = in_sizes[0] / 169;

    float* out   = (float*)d_out;
    float* outT  = out;                          // [N,4,4]
    float* outOm = out + (size_t)N * 16;         // [N,6,6]

    const int blocks = (N + NPB - 1) / NPB;
    mtm_refine_kernel<<<blocks, NT>>>(Min, Tin, outT, outOm, N);
}